// round 7
// baseline (speedup 1.0000x reference)
#include <cuda_runtime.h>
#include <cuda_fp16.h>
#include <cstdint>

// Problem constants
#define NIMG   128          // images per input
#define NTOT   256          // stacked rows (a then b)
#define CCH    16           // channels
#define HP     16           // pooled H
#define WP     16           // pooled W
#define DDIM   4096         // CCH*HP*WP
#define TILE   32           // pair tile edge
#define NTROW  8            // NTOT/TILE
#define NTILES 36           // upper-tri tiles: 8*9/2
#define DCHUNK 256          // d per block (pair kernel)
#define NDCH   16           // DDIM/DCHUNK
#define DSTEP  32           // smem staging depth
#define NSTEPS (DCHUNK / DSTEP)      // 8
#define NBLK_TOTAL (NTILES * NDCH)   // 576

// sqrt(0.5*log2(e)) folded into the pooled means so the inner loop needs no
// extra constant multiply: term = ex2(-(d'*r)^2) * r with d' = d*sqrt(k).
#define SQRT_K      0.8493218003f
#define MEAN_SCALE  (0.25f * SQRT_K)   // avgpool /4 fused with sqrt(k)

// Scratch: pooled mean/variance, TRANSPOSED layout [d][n] (n contiguous).
__device__ float g_Mt[DDIM * NTOT];
__device__ float g_Vt[DDIM * NTOT];
__device__ double g_acc;          // zero-init; reset by last block each run
__device__ unsigned int g_done;   // zero-init; reset by last block each run

__device__ __forceinline__ float rsqrt_approx(float x) {
    float y; asm("rsqrt.approx.ftz.f32 %0, %1;" : "=f"(y) : "f"(x)); return y;
}
__device__ __forceinline__ __half2 h2ex2(__half2 x) {
    unsigned xi = *reinterpret_cast<unsigned*>(&x), yi;
    asm("ex2.approx.f16x2 %0, %1;" : "=r"(yi) : "r"(xi));
    return *reinterpret_cast<__half2*>(&yi);
}

// ---------------------------------------------------------------------------
// Pooling: one block per (ph, c, array). 256 threads.
// ---------------------------------------------------------------------------
__global__ __launch_bounds__(256) void pool_kernel(
    const float* __restrict__ mu_a, const float* __restrict__ lv_a,
    const float* __restrict__ mu_b, const float* __restrict__ lv_b)
{
    const int ph  = blockIdx.x;      // 0..15
    const int c   = blockIdx.y;      // 0..15
    const int arr = blockIdx.z;      // 0..3
    const int tid = threadIdx.x;

    const float* src = (arr == 0) ? mu_a : (arr == 1) ? lv_a : (arr == 2) ? mu_b : lv_b;
    float* dst       = (arr & 1) ? g_Vt : g_Mt;
    const int n_off  = (arr < 2) ? 0 : NIMG;
    const bool isVar = (arr & 1);

    __shared__ float s[NIMG * 17];   // padded transpose buffer (n*17 + pw)

    const float2* src2 = reinterpret_cast<const float2*>(src);

    #pragma unroll
    for (int k = 0; k < 8; k++) {
        int o  = tid + 256 * k;      // 0..2047
        int n  = o >> 4;
        int pw = o & 15;
        int i2 = n * 8192 + c * 512 + ph * 32 + pw;
        float2 r0 = src2[i2];
        float2 r1 = src2[i2 + 16];
        float p;
        if (isVar) {
            p = (__expf(r0.x) + __expf(r0.y) + __expf(r1.x) + __expf(r1.y)) * 0.0625f;
        } else {
            p = (r0.x + r0.y + r1.x + r1.y) * MEAN_SCALE;
        }
        s[n * 17 + pw] = p;
    }
    __syncthreads();

    const int dbase = ((c * 16 + ph) * 16) * NTOT + n_off;
    #pragma unroll
    for (int k = 0; k < 8; k++) {
        int o  = tid + 256 * k;
        int pw = o >> 7;
        int n  = o & 127;
        dst[dbase + pw * NTOT + n] = s[n * 17 + pw];
    }
}

// ---------------------------------------------------------------------------
// Pair kernel: grid (36 upper-tri tiles, 16 d-chunks), 256 threads.
// Double-buffered smem, register prefetch, one __syncthreads per DSTEP.
// ex2 in f16x2 (shared across 2 terms); r kept f32; f32 FFMA accumulation.
// ---------------------------------------------------------------------------
__global__ __launch_bounds__(256) void pair_kernel(float* __restrict__ out)
{
    int rem = blockIdx.x;
    int ti = 0;
    while (rem >= NTROW - ti) { rem -= NTROW - ti; ti++; }
    const int tj = ti + rem;

    const int i0 = ti * TILE;
    const int j0 = tj * TILE;
    const int d0 = blockIdx.y * DCHUNK;

    const int tid  = threadIdx.x;
    const int jx   = tid & 15;       // j micro-col (pairs of 2)
    const int iy   = tid >> 4;       // i micro-row (pairs of 2)

    // double-buffered staging: [buf][array d-slice]
    __shared__ __align__(16) float sMi[2][DSTEP * TILE];
    __shared__ __align__(16) float sVi[2][DSTEP * TILE];
    __shared__ __align__(16) float sMj[2][DSTEP * TILE];
    __shared__ __align__(16) float sVj[2][DSTEP * TILE];
    __shared__ float warpsum[8];

    float acc00 = 0.f, acc01 = 0.f, acc10 = 0.f, acc11 = 0.f;

    // loader mapping: each thread owns one d-row (tid>>3) and a float4 lane
    const int lrow  = tid >> 3;          // 0..31
    const int lane4 = (tid & 7) * 4;     // 0,4,..,28

    float4 pf0, pf1, pf2, pf3;
    {
        int g = (d0 + lrow) * NTOT;
        pf0 = *reinterpret_cast<const float4*>(&g_Mt[g + i0 + lane4]);
        pf1 = *reinterpret_cast<const float4*>(&g_Vt[g + i0 + lane4]);
        pf2 = *reinterpret_cast<const float4*>(&g_Mt[g + j0 + lane4]);
        pf3 = *reinterpret_cast<const float4*>(&g_Vt[g + j0 + lane4]);
    }
    // stage chunk 0 into buffer 0
    {
        int o = lrow * TILE + lane4;
        *reinterpret_cast<float4*>(&sMi[0][o]) = pf0;
        *reinterpret_cast<float4*>(&sVi[0][o]) = pf1;
        *reinterpret_cast<float4*>(&sMj[0][o]) = pf2;
        *reinterpret_cast<float4*>(&sVj[0][o]) = pf3;
    }

    #pragma unroll
    for (int s = 0; s < NSTEPS; s++) {
        const int p = s & 1;
        __syncthreads();   // buffer p staged for all; compute (s-1) done everywhere

        // prefetch chunk s+1 from global (L2) — overlapped with compute below
        if (s + 1 < NSTEPS) {
            int g = (d0 + (s + 1) * DSTEP + lrow) * NTOT;
            pf0 = *reinterpret_cast<const float4*>(&g_Mt[g + i0 + lane4]);
            pf1 = *reinterpret_cast<const float4*>(&g_Vt[g + i0 + lane4]);
            pf2 = *reinterpret_cast<const float4*>(&g_Mt[g + j0 + lane4]);
            pf3 = *reinterpret_cast<const float4*>(&g_Vt[g + j0 + lane4]);
        }

        #pragma unroll 4
        for (int dd = 0; dd < DSTEP; dd++) {
            float2 mi = *reinterpret_cast<float2*>(&sMi[p][dd * TILE + 2 * iy]);
            float2 vi = *reinterpret_cast<float2*>(&sVi[p][dd * TILE + 2 * iy]);
            float2 mj = *reinterpret_cast<float2*>(&sMj[p][dd * TILE + 2 * jx]);
            float2 vj = *reinterpret_cast<float2*>(&sVj[p][dd * TILE + 2 * jx]);

            // row 0 (mi.x, vi.x) vs j-pair
            {
                float s0 = vi.x + vj.x, s1 = vi.x + vj.y;
                float r0 = rsqrt_approx(s0), r1 = rsqrt_approx(s1);
                float t0 = (mi.x - mj.x) * r0;
                float t1 = (mi.x - mj.y) * r1;
                __half2 e = h2ex2(__floats2half2_rn(-t0 * t0, -t1 * t1));
                acc00 = fmaf(__low2float(e),  r0, acc00);
                acc01 = fmaf(__high2float(e), r1, acc01);
            }
            // row 1 (mi.y, vi.y) vs j-pair
            {
                float s0 = vi.y + vj.x, s1 = vi.y + vj.y;
                float r0 = rsqrt_approx(s0), r1 = rsqrt_approx(s1);
                float t0 = (mi.y - mj.x) * r0;
                float t1 = (mi.y - mj.y) * r1;
                __half2 e = h2ex2(__floats2half2_rn(-t0 * t0, -t1 * t1));
                acc10 = fmaf(__low2float(e),  r0, acc10);
                acc11 = fmaf(__high2float(e), r1, acc11);
            }
        }

        // stage chunk s+1 into the other buffer (safe: sync at top of this
        // iter guaranteed everyone finished computing on it)
        if (s + 1 < NSTEPS) {
            int o = lrow * TILE + lane4;
            int q = 1 - p;
            *reinterpret_cast<float4*>(&sMi[q][o]) = pf0;
            *reinterpret_cast<float4*>(&sVi[q][o]) = pf1;
            *reinterpret_cast<float4*>(&sMj[q][o]) = pf2;
            *reinterpret_cast<float4*>(&sVj[q][o]) = pf3;
        }
    }

    // block reduce
    float v = (acc00 + acc01) + (acc10 + acc11);
    #pragma unroll
    for (int o = 16; o; o >>= 1) v += __shfl_xor_sync(0xffffffffu, v, o);
    if ((tid & 31) == 0) warpsum[tid >> 5] = v;
    __syncthreads();
    if (tid == 0) {
        float b = 0.f;
        #pragma unroll
        for (int k = 0; k < 8; k++) b += warpsum[k];
        double sgn = ((ti < 4) == (tj < 4)) ? 1.0 : -1.0;
        double w   = (ti == tj) ? sgn : 2.0 * sgn;
        atomicAdd(&g_acc, (double)b * w);
        __threadfence();
        unsigned n = atomicAdd(&g_done, 1u);
        if (n == NBLK_TOTAL - 1) {
            __threadfence();
            double total = *((volatile double*)&g_acc);
            out[0] = (float)total;
            // reset for the next (graph-replayed) run
            *((volatile double*)&g_acc) = 0.0;
            *((volatile unsigned*)&g_done) = 0u;
            __threadfence();
        }
    }
}

extern "C" void kernel_launch(void* const* d_in, const int* in_sizes, int n_in,
                              void* d_out, int out_size)
{
    const float* mu_a = (const float*)d_in[0];
    const float* lv_a = (const float*)d_in[1];
    const float* mu_b = (const float*)d_in[2];
    const float* lv_b = (const float*)d_in[3];
    float* out = (float*)d_out;

    pool_kernel<<<dim3(HP, CCH, 4), 256>>>(mu_a, lv_a, mu_b, lv_b);
    pair_kernel<<<dim3(NTILES, NDCH), 256>>>(out);
}

// round 9
// speedup vs baseline: 1.1564x; 1.1564x over previous
#include <cuda_runtime.h>
#include <cuda_fp16.h>
#include <cstdint>

// Problem constants
#define NIMG   128          // images per input
#define NTOT   256          // stacked rows (a then b)
#define CCH    16           // channels
#define HP     16           // pooled H
#define WP     16           // pooled W
#define DDIM   4096         // CCH*HP*WP
#define TILE   32           // pair tile edge
#define NTROW  8            // NTOT/TILE
#define NTILES 36           // upper-tri tiles: 8*9/2
#define DCHUNK 256          // d per block (pair kernel)
#define NDCH   16           // DDIM/DCHUNK
#define DSTEP  32           // smem staging depth
#define NSTEPS (DCHUNK / DSTEP)      // 8
#define NBLK_MAIN  (NTILES * NDCH)   // 576 main blocks
#define NBLK_COUNT (NBLK_MAIN + 1)   // + 1 bias-sampling block

// sqrt(0.5*log2(e)) folded into the pooled means: term = ex2(-(d'*r)^2) * r.
#define SQRT_K      0.8493218003f
#define MEAN_SCALE  (0.25f * SQRT_K)

// Scratch: pooled mean/variance, TRANSPOSED layout [d][n] (n contiguous).
__device__ float g_Mt[DDIM * NTOT];
__device__ float g_Vt[DDIM * NTOT];
__device__ double g_acc;          // zero-init; reset by last block each run
__device__ unsigned int g_done;   // zero-init; reset by last block each run

__device__ __forceinline__ float rsqrt_approx(float x) {
    float y; asm("rsqrt.approx.ftz.f32 %0, %1;" : "=f"(y) : "f"(x)); return y;
}
__device__ __forceinline__ float ex2f32(float x) {
    float y; asm("ex2.approx.ftz.f32 %0, %1;" : "=f"(y) : "f"(x)); return y;
}
__device__ __forceinline__ __half2 h2ex2(__half2 x) {
    unsigned xi = *reinterpret_cast<unsigned*>(&x), yi;
    asm("ex2.approx.f16x2 %0, %1;" : "=r"(yi) : "r"(xi));
    return *reinterpret_cast<__half2*>(&yi);
}

// ---------------------------------------------------------------------------
// Pooling: one block per (ph, c, array). 256 threads.
// ---------------------------------------------------------------------------
__global__ __launch_bounds__(256) void pool_kernel(
    const float* __restrict__ mu_a, const float* __restrict__ lv_a,
    const float* __restrict__ mu_b, const float* __restrict__ lv_b)
{
    const int ph  = blockIdx.x;      // 0..15
    const int c   = blockIdx.y;      // 0..15
    const int arr = blockIdx.z;      // 0..3
    const int tid = threadIdx.x;

    const float* src = (arr == 0) ? mu_a : (arr == 1) ? lv_a : (arr == 2) ? mu_b : lv_b;
    float* dst       = (arr & 1) ? g_Vt : g_Mt;
    const int n_off  = (arr < 2) ? 0 : NIMG;
    const bool isVar = (arr & 1);

    __shared__ float s[NIMG * 17];   // padded transpose buffer (n*17 + pw)

    const float2* src2 = reinterpret_cast<const float2*>(src);

    #pragma unroll
    for (int k = 0; k < 8; k++) {
        int o  = tid + 256 * k;      // 0..2047
        int n  = o >> 4;
        int pw = o & 15;
        int i2 = n * 8192 + c * 512 + ph * 32 + pw;
        float2 r0 = src2[i2];
        float2 r1 = src2[i2 + 16];
        float p;
        if (isVar) {
            p = (__expf(r0.x) + __expf(r0.y) + __expf(r1.x) + __expf(r1.y)) * 0.0625f;
        } else {
            p = (r0.x + r0.y + r1.x + r1.y) * MEAN_SCALE;
        }
        s[n * 17 + pw] = p;
    }
    __syncthreads();

    const int dbase = ((c * 16 + ph) * 16) * NTOT + n_off;
    #pragma unroll
    for (int k = 0; k < 8; k++) {
        int o  = tid + 256 * k;
        int pw = o >> 7;
        int n  = o & 127;
        dst[dbase + pw * NTOT + n] = s[n * 17 + pw];
    }
}

// ---------------------------------------------------------------------------
// Pair kernel: 576 main blocks (36 upper-tri tiles x 16 d-chunks) + 1 bias
// sampling block. Double-buffered smem, register prefetch, HFMA2 accumulate,
// fp16x2 ex2 shared across 2 terms.
//
// The fp16 ex2 path carries a small mean bias b per off-diagonal term; since
// sum_ij s_i s_j = 0 exactly, the signed sum of biases reduces to -256*bbar
// (diagonal terms are exact). Block NBLK_MAIN estimates bbar by running
// 256 sample pairs x 128 dims through BOTH paths and adds the correction
// +256*bbar_hat = +32*sum(f16-f32) to the accumulator.
// ---------------------------------------------------------------------------
__global__ __launch_bounds__(256) void pair_kernel(float* __restrict__ out)
{
    const int tid = threadIdx.x;
    __shared__ float warpsum[8];

    double myContribution = 0.0;   // this block's signed contribution

    if (blockIdx.x < NBLK_MAIN) {
        // ---- main pair block ----
        const int tileIdx = blockIdx.x % NTILES;
        const int dch     = blockIdx.x / NTILES;

        int rem = tileIdx;
        int ti = 0;
        while (rem >= NTROW - ti) { rem -= NTROW - ti; ti++; }
        const int tj = ti + rem;

        const int i0 = ti * TILE;
        const int j0 = tj * TILE;
        const int d0 = dch * DCHUNK;

        const int jx = tid & 15;        // j micro-col (pairs of 2)
        const int iy = tid >> 4;        // i micro-row (pairs of 2)

        __shared__ __align__(16) float sMi[2][DSTEP * TILE];
        __shared__ __align__(16) float sVi[2][DSTEP * TILE];
        __shared__ __align__(16) float sMj[2][DSTEP * TILE];
        __shared__ __align__(16) float sVj[2][DSTEP * TILE];

        float facc0 = 0.f, facc1 = 0.f;

        const int lrow  = tid >> 3;          // 0..31
        const int lane4 = (tid & 7) * 4;     // 0,4,..,28

        float4 pf0, pf1, pf2, pf3;
        {
            int g = (d0 + lrow) * NTOT;
            pf0 = *reinterpret_cast<const float4*>(&g_Mt[g + i0 + lane4]);
            pf1 = *reinterpret_cast<const float4*>(&g_Vt[g + i0 + lane4]);
            pf2 = *reinterpret_cast<const float4*>(&g_Mt[g + j0 + lane4]);
            pf3 = *reinterpret_cast<const float4*>(&g_Vt[g + j0 + lane4]);
        }
        {
            int o = lrow * TILE + lane4;
            *reinterpret_cast<float4*>(&sMi[0][o]) = pf0;
            *reinterpret_cast<float4*>(&sVi[0][o]) = pf1;
            *reinterpret_cast<float4*>(&sMj[0][o]) = pf2;
            *reinterpret_cast<float4*>(&sVj[0][o]) = pf3;
        }

        #pragma unroll
        for (int s = 0; s < NSTEPS; s++) {
            const int p = s & 1;
            __syncthreads();

            if (s + 1 < NSTEPS) {
                int g = (d0 + (s + 1) * DSTEP + lrow) * NTOT;
                pf0 = *reinterpret_cast<const float4*>(&g_Mt[g + i0 + lane4]);
                pf1 = *reinterpret_cast<const float4*>(&g_Vt[g + i0 + lane4]);
                pf2 = *reinterpret_cast<const float4*>(&g_Mt[g + j0 + lane4]);
                pf3 = *reinterpret_cast<const float4*>(&g_Vt[g + j0 + lane4]);
            }

            __half2 hacc0 = __floats2half2_rn(0.f, 0.f);
            __half2 hacc1 = __floats2half2_rn(0.f, 0.f);

            #pragma unroll 4
            for (int dd = 0; dd < DSTEP; dd++) {
                float2 mi = *reinterpret_cast<float2*>(&sMi[p][dd * TILE + 2 * iy]);
                float2 vi = *reinterpret_cast<float2*>(&sVi[p][dd * TILE + 2 * iy]);
                float2 mj = *reinterpret_cast<float2*>(&sMj[p][dd * TILE + 2 * jx]);
                float2 vj = *reinterpret_cast<float2*>(&sVj[p][dd * TILE + 2 * jx]);

                // row 0 (mi.x, vi.x) vs j-pair
                {
                    float s0 = vi.x + vj.x, s1 = vi.x + vj.y;
                    float r0 = rsqrt_approx(s0), r1 = rsqrt_approx(s1);
                    float t0 = (mi.x - mj.x) * r0;
                    float t1 = (mi.x - mj.y) * r1;
                    __half2 e = h2ex2(__floats2half2_rn(-t0 * t0, -t1 * t1));
                    hacc0 = __hfma2(e, __floats2half2_rn(r0, r1), hacc0);
                }
                // row 1 (mi.y, vi.y) vs j-pair
                {
                    float s0 = vi.y + vj.x, s1 = vi.y + vj.y;
                    float r0 = rsqrt_approx(s0), r1 = rsqrt_approx(s1);
                    float t0 = (mi.y - mj.x) * r0;
                    float t1 = (mi.y - mj.y) * r1;
                    __half2 e = h2ex2(__floats2half2_rn(-t0 * t0, -t1 * t1));
                    hacc1 = __hfma2(e, __floats2half2_rn(r0, r1), hacc1);
                }
            }

            facc0 += __low2float(hacc0) + __high2float(hacc0);
            facc1 += __low2float(hacc1) + __high2float(hacc1);

            if (s + 1 < NSTEPS) {
                int o = lrow * TILE + lane4;
                int q = 1 - p;
                *reinterpret_cast<float4*>(&sMi[q][o]) = pf0;
                *reinterpret_cast<float4*>(&sVi[q][o]) = pf1;
                *reinterpret_cast<float4*>(&sMj[q][o]) = pf2;
                *reinterpret_cast<float4*>(&sVj[q][o]) = pf3;
            }
        }

        // block reduce
        float v = facc0 + facc1;
        #pragma unroll
        for (int o = 16; o; o >>= 1) v += __shfl_xor_sync(0xffffffffu, v, o);
        if ((tid & 31) == 0) warpsum[tid >> 5] = v;
        __syncthreads();
        if (tid == 0) {
            float b = 0.f;
            #pragma unroll
            for (int k = 0; k < 8; k++) b += warpsum[k];
            double sgn = ((ti < 4) == (tj < 4)) ? 1.0 : -1.0;
            double w   = (ti == tj) ? sgn : 2.0 * sgn;
            myContribution = (double)b * w;
        }
    } else {
        // ---- bias sampling block ----
        // 256 sample pairs (tid, tid+1 mod 256) x 128 dims; both precisions.
        const int p0 = tid;
        const int p1 = (tid + 1) & 255;
        float S16 = 0.f, S32 = 0.f;

        #pragma unroll 1
        for (int db = 0; db < 128; db += 32) {
            __half2 hacc = __floats2half2_rn(0.f, 0.f);
            float s32 = 0.f;
            #pragma unroll
            for (int dd = 0; dd < 32; dd += 2) {
                int d = db + dd;
                float m00 = g_Mt[d * NTOT + p0],       m01 = g_Mt[d * NTOT + p1];
                float v00 = g_Vt[d * NTOT + p0],       v01 = g_Vt[d * NTOT + p1];
                float m10 = g_Mt[(d + 1) * NTOT + p0], m11 = g_Mt[(d + 1) * NTOT + p1];
                float v10 = g_Vt[(d + 1) * NTOT + p0], v11 = g_Vt[(d + 1) * NTOT + p1];

                float s0 = v00 + v01, s1 = v10 + v11;
                float r0 = rsqrt_approx(s0), r1 = rsqrt_approx(s1);
                float t0 = (m00 - m01) * r0;
                float t1 = (m10 - m11) * r1;
                float u0 = -t0 * t0, u1 = -t1 * t1;
                // f32 reference path
                s32 = fmaf(ex2f32(u0), r0, s32);
                s32 = fmaf(ex2f32(u1), r1, s32);
                // f16 path (identical ops to the main loop)
                __half2 e = h2ex2(__floats2half2_rn(u0, u1));
                hacc = __hfma2(e, __floats2half2_rn(r0, r1), hacc);
            }
            S16 += __low2float(hacc) + __high2float(hacc);
            S32 += s32;
        }

        float diff = S16 - S32;
        #pragma unroll
        for (int o = 16; o; o >>= 1) diff += __shfl_xor_sync(0xffffffffu, diff, o);
        if ((tid & 31) == 0) warpsum[tid >> 5] = diff;
        __syncthreads();
        if (tid == 0) {
            float dsum = 0.f;
            #pragma unroll
            for (int k = 0; k < 8; k++) dsum += warpsum[k];
            // correction = +256 * bbar = +256 * (4096/ (256*128)) * sum(diff)
            myContribution = 32.0 * (double)dsum;
        }
    }

    if (tid == 0) {
        atomicAdd(&g_acc, myContribution);
        __threadfence();
        unsigned n = atomicAdd(&g_done, 1u);
        if (n == NBLK_COUNT - 1) {
            __threadfence();
            double total = *((volatile double*)&g_acc);
            out[0] = (float)total;
            // reset for the next (graph-replayed) run
            *((volatile double*)&g_acc) = 0.0;
            *((volatile unsigned*)&g_done) = 0u;
            __threadfence();
        }
    }
}

extern "C" void kernel_launch(void* const* d_in, const int* in_sizes, int n_in,
                              void* d_out, int out_size)
{
    const float* mu_a = (const float*)d_in[0];
    const float* lv_a = (const float*)d_in[1];
    const float* mu_b = (const float*)d_in[2];
    const float* lv_b = (const float*)d_in[3];
    float* out = (float*)d_out;

    pool_kernel<<<dim3(HP, CCH, 4), 256>>>(mu_a, lv_a, mu_b, lv_b);
    pair_kernel<<<NBLK_COUNT, 256>>>(out);
}